// round 4
// baseline (speedup 1.0000x reference)
#include <cuda_runtime.h>

// Problem constants
#define BSZ   8192
#define NN    40
#define FF    256
#define NBLKC 4
#define BLKR  10
#define MROWS (BSZ*NN)          // 327680
#define JCOLS (NN*FF)           // 10240
#define EPSBN 1e-5f
#define NPART 64                // batch partials for deterministic stats

// Scratch (allocation-free rule: __device__ globals)
__device__ float g_Z[(size_t)MROWS*FF];      // 335.5 MB
__device__ float g_Y[(size_t)MROWS*FF];      // 335.5 MB
__device__ float g_psum[NPART*JCOLS];
__device__ float g_psq[NPART*JCOLS];
__device__ float g_scale[JCOLS];
__device__ float g_bias[JCOLS];

// ---------------------------------------------------------------------------
// K1: Z[b,n,:] = sum_m adj[b, n, m] * input[b, m, :]  (within 10x10 diag block)
// grid (BSZ, 4), 256 threads; thread = feature f
// ---------------------------------------------------------------------------
__global__ void k_z(const float* __restrict__ inp, const float* __restrict__ adj)
{
    int b = blockIdx.x, blk = blockIdx.y, t = threadIdx.x;
    __shared__ float a[BLKR][BLKR];
    if (t < BLKR*BLKR) {
        int r = t / BLKR, c = t % BLKR;
        a[r][c] = adj[(size_t)b*NN*NN + (size_t)(blk*BLKR + r)*NN + blk*BLKR + c];
    }
    float x[BLKR];
    const float* ip = inp + ((size_t)b*NN + blk*BLKR)*FF + t;
    #pragma unroll
    for (int m = 0; m < BLKR; m++) x[m] = ip[(size_t)m*FF];
    __syncthreads();
    float* zp = g_Z + ((size_t)b*NN + blk*BLKR)*FF + t;
    #pragma unroll
    for (int n = 0; n < BLKR; n++) {
        float acc = 0.f;
        #pragma unroll
        for (int m = 0; m < BLKR; m++) acc += a[n][m] * x[m];
        zp[(size_t)n*FF] = acc;
    }
}

// ---------------------------------------------------------------------------
// K2: Y = Z @ W   ([327680 x 256] @ [256 x 256]), fp32 SGEMM
// CTA tile 128x128, k-tile 8, 256 threads, 8x8 per-thread microtile
// ---------------------------------------------------------------------------
__global__ __launch_bounds__(256, 2) void k_gemm(const float* __restrict__ Wm)
{
    __shared__ float As[8*128];   // As[k][m] (transposed)
    __shared__ float Bs[8*128];   // Bs[k][n]

    int t   = threadIdx.x;
    int row0 = blockIdx.x * 128;
    int n0   = blockIdx.y * 128;
    int tx = t & 15, ty = t >> 4;

    int ar  = t >> 1;            // A tile row 0..127
    int ac4 = (t & 1) * 4;       // A tile k-col {0,4}
    int br  = t >> 5;            // B tile k-row 0..7
    int bc4 = (t & 31) * 4;      // B tile n-col

    float acc[8][8];
    #pragma unroll
    for (int i = 0; i < 8; i++)
        #pragma unroll
        for (int j = 0; j < 8; j++) acc[i][j] = 0.f;

    for (int kt = 0; kt < 256; kt += 8) {
        float4 av = *(const float4*)(g_Z + (size_t)(row0 + ar)*256 + kt + ac4);
        float4 bv = *(const float4*)(Wm  + (size_t)(kt + br)*256 + n0 + bc4);
        __syncthreads();
        As[(ac4+0)*128 + ar] = av.x;
        As[(ac4+1)*128 + ar] = av.y;
        As[(ac4+2)*128 + ar] = av.z;
        As[(ac4+3)*128 + ar] = av.w;
        *(float4*)(Bs + br*128 + bc4) = bv;
        __syncthreads();
        #pragma unroll
        for (int k = 0; k < 8; k++) {
            float4 a0 = *(float4*)(As + k*128 + ty*8);
            float4 a1 = *(float4*)(As + k*128 + ty*8 + 4);
            float4 b0 = *(float4*)(Bs + k*128 + tx*8);
            float4 b1 = *(float4*)(Bs + k*128 + tx*8 + 4);
            float af[8] = {a0.x,a0.y,a0.z,a0.w,a1.x,a1.y,a1.z,a1.w};
            float bf[8] = {b0.x,b0.y,b0.z,b0.w,b1.x,b1.y,b1.z,b1.w};
            #pragma unroll
            for (int i = 0; i < 8; i++)
                #pragma unroll
                for (int j = 0; j < 8; j++)
                    acc[i][j] += af[i] * bf[j];
        }
    }

    #pragma unroll
    for (int i = 0; i < 8; i++) {
        float4 v0 = {acc[i][0], acc[i][1], acc[i][2], acc[i][3]};
        float4 v1 = {acc[i][4], acc[i][5], acc[i][6], acc[i][7]};
        float* cp = g_Y + (size_t)(row0 + ty*8 + i)*256 + n0 + tx*8;
        *(float4*)(cp)     = v0;
        *(float4*)(cp + 4) = v1;
    }
}

// ---------------------------------------------------------------------------
// K3: deterministic partial sums over the batch dim per column j = n*256+f
// grid (JCOLS/256 = 40, NPART), 256 threads
// ---------------------------------------------------------------------------
__global__ void k_stats()
{
    int j = blockIdx.x * 256 + threadIdx.x;
    int p = blockIdx.y;
    const int bper = BSZ / NPART;           // 128
    const float* yp = g_Y + (size_t)p * bper * JCOLS + j;
    float s = 0.f, q = 0.f;
    for (int b = 0; b < bper; b++) {
        float v = yp[(size_t)b * JCOLS];
        s += v; q += v * v;
    }
    g_psum[p*JCOLS + j] = s;
    g_psq [p*JCOLS + j] = q;
}

// ---------------------------------------------------------------------------
// K4: finalize per-column scale/bias
// out[b,j] = (Y-mean)*rsqrt(var+eps)*gamma[blk(n),j] + sum_i beta[i,j]
//          = Y*scale[j] + bias[j]
// ---------------------------------------------------------------------------
__global__ void k_finalize(const float* __restrict__ gamma, const float* __restrict__ beta)
{
    int j = blockIdx.x * 256 + threadIdx.x;
    float s = 0.f, q = 0.f;
    for (int p = 0; p < NPART; p++) {
        s += g_psum[p*JCOLS + j];
        q += g_psq [p*JCOLS + j];
    }
    const float invB = 1.f / (float)BSZ;
    float mean = s * invB;
    float var  = q * invB - mean * mean;
    int n = j / FF;
    int blk = n / BLKR;
    float sc = rsqrtf(var + EPSBN) * gamma[blk*JCOLS + j];
    float bs = 0.f;
    #pragma unroll
    for (int i = 0; i < NBLKC; i++) bs += beta[i*JCOLS + j];
    g_scale[j] = sc;
    g_bias[j]  = bs - mean * sc;
}

// ---------------------------------------------------------------------------
// K5: elementwise epilogue, float4-vectorized
// ---------------------------------------------------------------------------
__global__ void k_out(float* __restrict__ out)
{
    size_t idx = ((size_t)blockIdx.x * 256 + threadIdx.x) * 4;
    int j = (int)(idx % JCOLS);
    float4 y  = *(const float4*)(g_Y + idx);
    float4 sc = *(const float4*)(g_scale + j);
    float4 bs = *(const float4*)(g_bias + j);
    float4 o;
    o.x = y.x*sc.x + bs.x;
    o.y = y.y*sc.y + bs.y;
    o.z = y.z*sc.z + bs.z;
    o.w = y.w*sc.w + bs.w;
    *(float4*)(out + idx) = o;
}

// ---------------------------------------------------------------------------
extern "C" void kernel_launch(void* const* d_in, const int* in_sizes, int n_in,
                              void* d_out, int out_size)
{
    const float* inp   = (const float*)d_in[0];
    const float* adj   = (const float*)d_in[1];
    const float* Wm    = (const float*)d_in[2];
    const float* gamma = (const float*)d_in[3];
    const float* beta  = (const float*)d_in[4];
    float* out = (float*)d_out;

    k_z      <<<dim3(BSZ, NBLKC), 256>>>(inp, adj);
    k_gemm   <<<dim3(MROWS/128, FF/128), 256>>>(Wm);
    k_stats  <<<dim3(JCOLS/256, NPART), 256>>>();
    k_finalize<<<JCOLS/256, 256>>>(gamma, beta);
    k_out    <<<(MROWS*FF/4)/256, 256>>>(out);
}

// round 6
// speedup vs baseline: 1.7667x; 1.7667x over previous
#include <cuda_runtime.h>
#include <cuda_bf16.h>
#include <cstdint>

// Problem constants
#define BSZ   8192
#define NN    40
#define FF    256
#define NBLKC 4
#define BLKR  10
#define MROWS (BSZ*NN)          // 327680
#define JCOLS (NN*FF)           // 10240
#define EPSBN 1e-5f
#define NPART 64

// Scratch (allocation-free rule: __device__ globals)
__device__ __nv_bfloat16 g_Zhi[(size_t)MROWS*FF];   // 167.8 MB
__device__ __nv_bfloat16 g_Zlo[(size_t)MROWS*FF];   // 167.8 MB
__device__ __nv_bfloat16 g_Wthi[FF*FF];             // W^T hi, [N][K]
__device__ __nv_bfloat16 g_Wtlo[FF*FF];             // W^T lo
__device__ float g_Y[(size_t)MROWS*FF];             // 335.5 MB
__device__ float g_psum[NPART*JCOLS];
__device__ float g_psq[NPART*JCOLS];
__device__ float g_scale[JCOLS];
__device__ float g_bias[JCOLS];

// ---------------------------------------------------------------------------
// helpers (baseline compute_103 PTX only: mma.sync + ldmatrix + cp.async)
// ---------------------------------------------------------------------------
__device__ __forceinline__ uint32_t smem_to_u32(const void* p) {
    uint32_t a;
    asm("{ .reg .u64 t; cvta.to.shared.u64 t, %1; cvt.u32.u64 %0, t; }" : "=r"(a) : "l"(p));
    return a;
}
__device__ __forceinline__ void ldm_x4(uint32_t& r0, uint32_t& r1, uint32_t& r2, uint32_t& r3,
                                       uint32_t addr) {
    asm volatile("ldmatrix.sync.aligned.m8n8.x4.shared.b16 {%0,%1,%2,%3}, [%4];"
                 : "=r"(r0), "=r"(r1), "=r"(r2), "=r"(r3) : "r"(addr));
}
__device__ __forceinline__ void mma_bf16(float* d, const uint32_t* a, const uint32_t* b) {
    asm volatile("mma.sync.aligned.m16n8k16.row.col.f32.bf16.bf16.f32 "
                 "{%0,%1,%2,%3}, {%4,%5,%6,%7}, {%8,%9}, {%0,%1,%2,%3};"
                 : "+f"(d[0]), "+f"(d[1]), "+f"(d[2]), "+f"(d[3])
                 : "r"(a[0]), "r"(a[1]), "r"(a[2]), "r"(a[3]), "r"(b[0]), "r"(b[1]));
}
#define CP_ASYNC16(dst, src) \
    asm volatile("cp.async.cg.shared.global [%0], [%1], 16;" :: "r"(dst), "l"(src))
#define CP_COMMIT() asm volatile("cp.async.commit_group;" ::: "memory")
#define CP_WAIT(n)  asm volatile("cp.async.wait_group %0;" :: "n"(n) : "memory")

// ---------------------------------------------------------------------------
// K1: Z = blockdiag(adj) @ input, emitted as bf16 hi/lo pair
// ---------------------------------------------------------------------------
__global__ void k_z(const float* __restrict__ inp, const float* __restrict__ adj)
{
    int b = blockIdx.x, blk = blockIdx.y, t = threadIdx.x;
    __shared__ float a[BLKR][BLKR];
    if (t < BLKR*BLKR) {
        int r = t / BLKR, c = t % BLKR;
        a[r][c] = adj[(size_t)b*NN*NN + (size_t)(blk*BLKR + r)*NN + blk*BLKR + c];
    }
    float x[BLKR];
    const float* ip = inp + ((size_t)b*NN + blk*BLKR)*FF + t;
    #pragma unroll
    for (int m = 0; m < BLKR; m++) x[m] = ip[(size_t)m*FF];
    __syncthreads();
    size_t base = ((size_t)b*NN + blk*BLKR)*FF + t;
    #pragma unroll
    for (int n = 0; n < BLKR; n++) {
        float acc = 0.f;
        #pragma unroll
        for (int m = 0; m < BLKR; m++) acc += a[n][m] * x[m];
        __nv_bfloat16 h = __float2bfloat16(acc);
        float r = acc - __bfloat162float(h);
        g_Zhi[base + (size_t)n*FF] = h;
        g_Zlo[base + (size_t)n*FF] = __float2bfloat16(r);
    }
}

// ---------------------------------------------------------------------------
// K1b: W [K,N] -> W^T hi/lo bf16 [N][K]
// ---------------------------------------------------------------------------
__global__ void k_wprep(const float* __restrict__ W)
{
    int n = blockIdx.x, k = threadIdx.x;
    float v = W[(size_t)k*FF + n];
    __nv_bfloat16 h = __float2bfloat16(v);
    float r = v - __bfloat162float(h);
    g_Wthi[n*FF + k] = h;
    g_Wtlo[n*FF + k] = __float2bfloat16(r);
}

// ---------------------------------------------------------------------------
// K2: Y = Z @ W via mma.sync bf16 hi/lo split (3 products, fp32 acc)
// CTA 128x128, k-tile 32, 8 warps (warp tile 64x32), cp.async 2-stage pipeline
// SMEM stage: Ahi|Alo|Bhi|Blo, each 128 rows x 40 halves (80B padded stride)
// ---------------------------------------------------------------------------
#define KT      32
#define ROWH    40                    // halves per padded row
#define TILE_B  (128*ROWH*2)          // 10240 B
#define STAGE_B (4*TILE_B)            // 40960 B
#define GSMEM   (2*STAGE_B)           // 81920 B

__global__ __launch_bounds__(256, 1) void k_gemm_mma()
{
    extern __shared__ __align__(16) char smem[];
    uint32_t sb = smem_to_u32(smem);
    int t = threadIdx.x, lane = t & 31, wid = t >> 5;
    int wm = wid & 1, wn = wid >> 1;          // warp tile: rows wm*64, cols wn*32
    int n0 = blockIdx.x * 128;                // N half (0 or 128)
    size_t m0 = (size_t)blockIdx.y * 128;

    const __nv_bfloat16* src0 = g_Zhi  + m0 * 256;
    const __nv_bfloat16* src1 = g_Zlo  + m0 * 256;
    const __nv_bfloat16* src2 = g_Wthi + (size_t)n0 * 256;
    const __nv_bfloat16* src3 = g_Wtlo + (size_t)n0 * 256;

    // per-thread fixed load decomposition (8 chunks of 16B per stage)
    // cid = t + i*256; buf = cid>>9, r = (cid>>2)&127, seg = cid&3
    float acc[4][4][4];
    #pragma unroll
    for (int a = 0; a < 4; a++)
        #pragma unroll
        for (int b = 0; b < 4; b++)
            #pragma unroll
            for (int c = 0; c < 4; c++) acc[a][b][c] = 0.f;

    #define LOAD_STAGE(kc, s) do {                                              \
        uint32_t _base = sb + (s) * STAGE_B;                                     \
        _Pragma("unroll")                                                        \
        for (int _i = 0; _i < 8; _i++) {                                         \
            int _cid = t + _i * 256;                                             \
            int _buf = _cid >> 9, _r = (_cid >> 2) & 127, _seg = _cid & 3;       \
            const __nv_bfloat16* _gp =                                           \
                (_buf == 0 ? src0 : _buf == 1 ? src1 : _buf == 2 ? src2 : src3)  \
                + (size_t)_r * 256 + (kc) * KT + _seg * 8;                       \
            uint32_t _dp = _base + _buf * TILE_B + (_r * ROWH + _seg * 8) * 2;   \
            CP_ASYNC16(_dp, _gp);                                                \
        } } while (0)

    LOAD_STAGE(0, 0);
    CP_COMMIT();

    for (int c = 0; c < 8; c++) {
        int cur = c & 1;
        if (c < 7) { LOAD_STAGE(c + 1, cur ^ 1); }
        CP_COMMIT();
        if (c < 7) CP_WAIT(1); else CP_WAIT(0);
        __syncthreads();

        uint32_t sAh = sb + cur * STAGE_B;
        uint32_t sAl = sAh + TILE_B;
        uint32_t sBh = sAh + 2 * TILE_B;
        uint32_t sBl = sAh + 3 * TILE_B;

        #pragma unroll
        for (int kk = 0; kk < KT; kk += 16) {
            uint32_t ah[4][4], al[4][4], bh[4][2], bl[4][2];
            // A fragments: lanes 0-7 rows m..m+7 @k, 8-15 rows m+8.. @k, 16-23 rows m.. @k+8, 24-31 m+8.. @k+8
            int arow = ((lane >> 3) & 1) * 8 + (lane & 7);
            int akoff = (lane >> 4) * 8 + kk;
            #pragma unroll
            for (int mi = 0; mi < 4; mi++) {
                uint32_t off = (uint32_t)((wm * 64 + mi * 16 + arow) * ROWH + akoff) * 2;
                ldm_x4(ah[mi][0], ah[mi][1], ah[mi][2], ah[mi][3], sAh + off);
                ldm_x4(al[mi][0], al[mi][1], al[mi][2], al[mi][3], sAl + off);
            }
            // B fragments: q=lane>>3: n = wn*32 + g*16 + (q>>1)*8 + lane&7, k += (q&1)*8
            int q = lane >> 3;
            int brow = (q >> 1) * 8 + (lane & 7);
            int bko = (q & 1) * 8 + kk;
            #pragma unroll
            for (int g = 0; g < 2; g++) {
                uint32_t off = (uint32_t)((wn * 32 + g * 16 + brow) * ROWH + bko) * 2;
                uint32_t r0, r1, r2, r3;
                ldm_x4(r0, r1, r2, r3, sBh + off);
                bh[2*g][0] = r0; bh[2*g][1] = r1; bh[2*g+1][0] = r2; bh[2*g+1][1] = r3;
                ldm_x4(r0, r1, r2, r3, sBl + off);
                bl[2*g][0] = r0; bl[2*g][1] = r1; bl[2*g+1][0] = r2; bl[2*g+1][1] = r3;
            }
            #pragma unroll
            for (int mi = 0; mi < 4; mi++)
                #pragma unroll
                for (int nj = 0; nj < 4; nj++) {
                    mma_bf16(acc[mi][nj], ah[mi], bh[nj]);   // hi*hi
                    mma_bf16(acc[mi][nj], ah[mi], bl[nj]);   // hi*lo
                    mma_bf16(acc[mi][nj], al[mi], bh[nj]);   // lo*hi
                }
        }
        __syncthreads();
    }

    // Epilogue: mma C fragment -> g_Y
    int r_in = lane >> 2, c2 = (lane & 3) * 2;
    #pragma unroll
    for (int mi = 0; mi < 4; mi++) {
        #pragma unroll
        for (int nj = 0; nj < 4; nj++) {
            size_t row = m0 + wm * 64 + mi * 16 + r_in;
            int col = n0 + wn * 32 + nj * 8 + c2;
            float2 v01 = {acc[mi][nj][0], acc[mi][nj][1]};
            float2 v23 = {acc[mi][nj][2], acc[mi][nj][3]};
            *(float2*)(g_Y + row * 256 + col)       = v01;
            *(float2*)(g_Y + (row + 8) * 256 + col) = v23;
        }
    }
}

// ---------------------------------------------------------------------------
// K3: deterministic partial sums over batch dim per column j
// ---------------------------------------------------------------------------
__global__ void k_stats()
{
    int j = blockIdx.x * 256 + threadIdx.x;
    int p = blockIdx.y;
    const int bper = BSZ / NPART;           // 128
    const float* yp = g_Y + (size_t)p * bper * JCOLS + j;
    float s = 0.f, q = 0.f;
    for (int b = 0; b < bper; b++) {
        float v = yp[(size_t)b * JCOLS];
        s += v; q += v * v;
    }
    g_psum[p*JCOLS + j] = s;
    g_psq [p*JCOLS + j] = q;
}

// ---------------------------------------------------------------------------
// K4: finalize per-column scale/bias
// ---------------------------------------------------------------------------
__global__ void k_finalize(const float* __restrict__ gamma, const float* __restrict__ beta)
{
    int j = blockIdx.x * 256 + threadIdx.x;
    float s = 0.f, q = 0.f;
    for (int p = 0; p < NPART; p++) {
        s += g_psum[p*JCOLS + j];
        q += g_psq [p*JCOLS + j];
    }
    const float invB = 1.f / (float)BSZ;
    float mean = s * invB;
    float var  = q * invB - mean * mean;
    int n = j / FF;
    int blk = n / BLKR;
    float sc = rsqrtf(var + EPSBN) * gamma[blk*JCOLS + j];
    float bs = 0.f;
    #pragma unroll
    for (int i = 0; i < NBLKC; i++) bs += beta[i*JCOLS + j];
    g_scale[j] = sc;
    g_bias[j]  = bs - mean * sc;
}

// ---------------------------------------------------------------------------
// K5: elementwise epilogue
// ---------------------------------------------------------------------------
__global__ void k_out(float* __restrict__ out)
{
    size_t idx = ((size_t)blockIdx.x * 256 + threadIdx.x) * 4;
    int j = (int)(idx % JCOLS);
    float4 y  = *(const float4*)(g_Y + idx);
    float4 sc = *(const float4*)(g_scale + j);
    float4 bs = *(const float4*)(g_bias + j);
    float4 o;
    o.x = y.x*sc.x + bs.x;
    o.y = y.y*sc.y + bs.y;
    o.z = y.z*sc.z + bs.z;
    o.w = y.w*sc.w + bs.w;
    *(float4*)(out + idx) = o;
}

// ---------------------------------------------------------------------------
extern "C" void kernel_launch(void* const* d_in, const int* in_sizes, int n_in,
                              void* d_out, int out_size)
{
    const float* inp   = (const float*)d_in[0];
    const float* adj   = (const float*)d_in[1];
    const float* Wm    = (const float*)d_in[2];
    const float* gamma = (const float*)d_in[3];
    const float* beta  = (const float*)d_in[4];
    float* out = (float*)d_out;

    cudaFuncSetAttribute(k_gemm_mma, cudaFuncAttributeMaxDynamicSharedMemorySize, GSMEM);

    k_z       <<<dim3(BSZ, NBLKC), 256>>>(inp, adj);
    k_wprep   <<<FF, FF>>>(Wm);
    k_gemm_mma<<<dim3(2, MROWS/128), 256, GSMEM>>>();
    k_stats   <<<dim3(JCOLS/256, NPART), 256>>>();
    k_finalize<<<JCOLS/256, 256>>>(gamma, beta);
    k_out     <<<(MROWS*FF/4)/256, 256>>>(out);
}